// round 1
// baseline (speedup 1.0000x reference)
#include <cuda_runtime.h>

// MultiLayerRNNModel: 2-layer tanh RNN
// T=2048, B=4096, I=3, H=5
// Inputs (metadata order): x[T,B,I], hx[2,B,H], w_ih0[H,I], w_hh0[H,H],
//   b_ih0[H], b_hh0[H], w_ih1[H,H], w_hh1[H,H], b_ih1[H], b_hh1[H]
// Output: out[T,B,H] followed by h_n[2,B,H]
//
// Strategy: one thread per (batch, hidden_unit). Groups of 8 lanes per batch
// (lanes 0..4 active). Each lane owns one output unit per layer; full state
// vectors are rebroadcast each step with __shfl_sync. tanh via MUFU.TANH
// (tanh.approx.f32). x is streamed through an 8-deep register prefetch
// pipeline to hide DRAM latency (~600cyc ~= 10 steps).

#define T_LEN 2048
#define B_SZ  4096
#define PF    8

__device__ __forceinline__ float tanh_fast(float x) {
    float y;
    asm("tanh.approx.f32 %0, %1;" : "=f"(y) : "f"(x));
    return y;
}

__global__ __launch_bounds__(224, 1)
void rnn2_kernel(const float* __restrict__ x,
                 const float* __restrict__ hx,
                 const float* __restrict__ w_ih0,
                 const float* __restrict__ w_hh0,
                 const float* __restrict__ b_ih0,
                 const float* __restrict__ b_hh0,
                 const float* __restrict__ w_ih1,
                 const float* __restrict__ w_hh1,
                 const float* __restrict__ b_ih1,
                 const float* __restrict__ b_hh1,
                 float* __restrict__ out)
{
    const int tid  = blockIdx.x * blockDim.x + threadIdx.x;
    const int b    = tid >> 3;                 // batch element
    const int lane = threadIdx.x & 31;
    const int j    = lane & 7;                 // hidden unit (active j<5)
    const int base = lane & ~7;                // group base lane within warp
    const bool bval = (b < B_SZ);
    const bool act  = bval && (j < 5);
    const int  jj   = (j < 5) ? j : 0;         // clamp for weight loads

    // ---- per-lane weights (row jj of each matrix) ----
    float wi0[3], wh0[5], wi1[5], wh1[5];
    #pragma unroll
    for (int k = 0; k < 3; k++) wi0[k] = w_ih0[jj * 3 + k];
    #pragma unroll
    for (int k = 0; k < 5; k++) {
        wh0[k] = w_hh0[jj * 5 + k];
        wi1[k] = w_ih1[jj * 5 + k];
        wh1[k] = w_hh1[jj * 5 + k];
    }
    const float bias0 = b_ih0[jj] + b_hh0[jj];
    const float bias1 = b_ih1[jj] + b_hh1[jj];

    // ---- initial state (replicated full vectors per lane) ----
    float h0v[5], h1v[5];
    #pragma unroll
    for (int k = 0; k < 5; k++) {
        h0v[k] = bval ? hx[b * 5 + k]              : 0.f;
        h1v[k] = bval ? hx[B_SZ * 5 + b * 5 + k]   : 0.f;
    }

    // ---- x prefetch pipeline (PF steps deep) ----
    float xq0[PF], xq1[PF], xq2[PF];
    #pragma unroll
    for (int p = 0; p < PF; p++) {
        const float* xp = x + (size_t)p * (B_SZ * 3) + b * 3;
        xq0[p] = bval ? xp[0] : 0.f;
        xq1[p] = bval ? xp[1] : 0.f;
        xq2[p] = bval ? xp[2] : 0.f;
    }

    float h0j = h0v[jj];
    float h1j = h1v[jj];

    for (int t0 = 0; t0 < T_LEN; t0 += PF) {
        #pragma unroll
        for (int p = 0; p < PF; p++) {
            const int t = t0 + p;
            const float x0 = xq0[p], x1 = xq1[p], x2 = xq2[p];

            // prefetch x[t+PF] into this slot
            const int tn = t + PF;
            if (tn < T_LEN && bval) {
                const float* xp = x + (size_t)tn * (B_SZ * 3) + b * 3;
                xq0[p] = xp[0];
                xq1[p] = xp[1];
                xq2[p] = xp[2];
            }

            // ---- layer 0: h0 = tanh(W_ih0 x + b0 + W_hh0 h0) ----
            // x-projection is off the recurrence critical path
            float pre = fmaf(wi0[2], x2, fmaf(wi0[1], x1, fmaf(wi0[0], x0, bias0)));
            float s0  = fmaf(wh0[1], h0v[1], fmaf(wh0[0], h0v[0], pre));
            float s1  = fmaf(wh0[4], h0v[4], fmaf(wh0[3], h0v[3], wh0[2] * h0v[2]));
            h0j = tanh_fast(s0 + s1);

            #pragma unroll
            for (int k = 0; k < 5; k++)
                h0v[k] = __shfl_sync(0xffffffffu, h0j, base + k);

            // ---- layer 1: h1 = tanh(W_ih1 h0 + b1 + W_hh1 h1) ----
            float u0 = fmaf(wi1[1], h0v[1], fmaf(wi1[0], h0v[0], bias1));
            float u1 = fmaf(wi1[4], h0v[4], fmaf(wi1[3], h0v[3], wi1[2] * h0v[2]));
            float v0 = fmaf(wh1[1], h1v[1], fmaf(wh1[0], h1v[0], wh1[2] * h1v[2]));
            float v1 = fmaf(wh1[4], h1v[4], wh1[3] * h1v[3]);
            h1j = tanh_fast((u0 + u1) + (v0 + v1));

            #pragma unroll
            for (int k = 0; k < 5; k++)
                h1v[k] = __shfl_sync(0xffffffffu, h1j, base + k);

            if (act)
                out[(size_t)t * (B_SZ * 5) + b * 5 + j] = h1j;
        }
    }

    // ---- h_n[2, B, H] ----
    if (act) {
        out[(size_t)T_LEN * (B_SZ * 5) + b * 5 + j]             = h0j;
        out[(size_t)T_LEN * (B_SZ * 5) + B_SZ * 5 + b * 5 + j]  = h1j;
    }
}

extern "C" void kernel_launch(void* const* d_in, const int* in_sizes, int n_in,
                              void* d_out, int out_size)
{
    const float* x     = (const float*)d_in[0];
    const float* hx    = (const float*)d_in[1];
    const float* w_ih0 = (const float*)d_in[2];
    const float* w_hh0 = (const float*)d_in[3];
    const float* b_ih0 = (const float*)d_in[4];
    const float* b_hh0 = (const float*)d_in[5];
    const float* w_ih1 = (const float*)d_in[6];
    const float* w_hh1 = (const float*)d_in[7];
    const float* b_ih1 = (const float*)d_in[8];
    const float* b_hh1 = (const float*)d_in[9];
    float* out = (float*)d_out;

    const int threads = 224;                       // 7 warps, 28 batch groups
    const int total   = B_SZ * 8;                  // 8 lanes per batch
    const int blocks  = (total + threads - 1) / threads;  // 147

    rnn2_kernel<<<blocks, threads>>>(x, hx, w_ih0, w_hh0, b_ih0, b_hh0,
                                     w_ih1, w_hh1, b_ih1, b_hh1, out);
}

// round 2
// speedup vs baseline: 1.0582x; 1.0582x over previous
#include <cuda_runtime.h>

// MultiLayerRNNModel: 2-layer tanh RNN, T=2048, B=4096, I=3, H=5
// out = concat(out[T,B,H], h_n[2,B,H])
//
// R2: software-pipelined layers. Iteration t computes h0(t) AND h1(t-1);
// the two tanh+shfl dependency chains are independent and overlap, halving
// the per-step critical path vs the serialized form.
// 8 lanes per batch (j<5 active), width-8 immediate shuffles, x streamed
// through an 8-deep register prefetch queue with compile-time phase indices.

#define T_LEN   2048
#define B_SZ    4096
#define XSTRIDE (B_SZ * 3)
#define OSTRIDE (B_SZ * 5)

__device__ __forceinline__ float tanh_fast(float v) {
    float y;
    asm("tanh.approx.f32 %0, %1;" : "=f"(y) : "f"(v));
    return y;
}

__global__ __launch_bounds__(224, 1)
void rnn2_kernel(const float* __restrict__ x,
                 const float* __restrict__ hx,
                 const float* __restrict__ w_ih0,
                 const float* __restrict__ w_hh0,
                 const float* __restrict__ b_ih0,
                 const float* __restrict__ b_hh0,
                 const float* __restrict__ w_ih1,
                 const float* __restrict__ w_hh1,
                 const float* __restrict__ b_ih1,
                 const float* __restrict__ b_hh1,
                 float* __restrict__ out)
{
    const int tid  = blockIdx.x * blockDim.x + threadIdx.x;
    const int b    = tid >> 3;                 // batch element
    const int j    = threadIdx.x & 7;          // hidden unit (active j<5)
    const bool bval = (b < B_SZ);
    const bool act  = bval && (j < 5);
    const int  jj   = (j < 5) ? j : 0;

    // per-lane weights (row jj)
    float wi0[3], wh0[5], wi1[5], wh1[5];
    #pragma unroll
    for (int k = 0; k < 3; k++) wi0[k] = w_ih0[jj * 3 + k];
    #pragma unroll
    for (int k = 0; k < 5; k++) {
        wh0[k] = w_hh0[jj * 5 + k];
        wi1[k] = w_ih1[jj * 5 + k];
        wh1[k] = w_hh1[jj * 5 + k];
    }
    const float bias0 = b_ih0[jj] + b_hh0[jj];
    const float bias1 = b_ih1[jj] + b_hh1[jj];

    // replicated state vectors: h0v = h0(t-1), h1v = h1(t-2) at loop head
    float h0v[5], h1v[5];
    #pragma unroll
    for (int k = 0; k < 5; k++) {
        h0v[k] = bval ? hx[b * 5 + k]            : 0.f;
        h1v[k] = bval ? hx[B_SZ * 5 + b * 5 + k] : 0.f;
    }

    const float* xb   = x + b * 3;
    float*       outp = out + b * 5 + j;

    // x prefetch queue, slot p holds x[t] with t&7 == p
    float xq0[8], xq1[8], xq2[8];
    #pragma unroll
    for (int p = 0; p < 8; p++) {
        const float* xp = xb + p * XSTRIDE;
        xq0[p] = bval ? xp[0] : 0.f;
        xq1[p] = bval ? xp[1] : 0.f;
        xq2[p] = bval ? xp[2] : 0.f;
    }

    float h0j = 0.f, h1j = 0.f;

// One pipelined step: computes h0(t) and h1(t-1). P == t&7 (compile-time).
#define STEP(t, P) {                                                          \
    const float x0 = xq0[P], x1 = xq1[P], x2 = xq2[P];                        \
    if (bval && (t) + 8 < T_LEN) {                                            \
        const float* xp = xb + ((t) + 8) * XSTRIDE;                           \
        xq0[P] = xp[0]; xq1[P] = xp[1]; xq2[P] = xp[2];                       \
    }                                                                         \
    /* layer-0 pre-activation (x-proj off critical path) */                  \
    const float pre = fmaf(wi0[2], x2, fmaf(wi0[1], x1, fmaf(wi0[0], x0, bias0))); \
    const float a0 = fmaf(wh0[0], h0v[0], pre);                               \
    const float a1 = fmaf(wh0[2], h0v[2], wh0[1] * h0v[1]);                   \
    const float a2 = fmaf(wh0[4], h0v[4], wh0[3] * h0v[3]);                   \
    const float s  = (a0 + a1) + a2;                                          \
    /* layer-1 pre-activation for h1(t-1): uses h0v=h0(t-1), h1v=h1(t-2) */   \
    const float ua = fmaf(wi1[0], h0v[0], bias1);                             \
    const float ub = fmaf(wi1[2], h0v[2], wi1[1] * h0v[1]);                   \
    const float uc = fmaf(wi1[4], h0v[4], wi1[3] * h0v[3]);                   \
    const float va = fmaf(wh1[1], h1v[1], wh1[0] * h1v[0]);                   \
    const float vb = fmaf(wh1[4], h1v[4], fmaf(wh1[3], h1v[3], wh1[2] * h1v[2])); \
    const float u  = ((ua + ub) + uc) + (va + vb);                            \
    h0j = tanh_fast(s);                                                       \
    h1j = tanh_fast(u);                                                       \
    _Pragma("unroll")                                                         \
    for (int k = 0; k < 5; k++) h0v[k] = __shfl_sync(0xffffffffu, h0j, k, 8); \
    _Pragma("unroll")                                                         \
    for (int k = 0; k < 5; k++) h1v[k] = __shfl_sync(0xffffffffu, h1j, k, 8); \
    if (act) outp[((t) - 1) * OSTRIDE] = h1j;                                 \
}

    // ---- prologue: t = 0, layer 0 only (h1v must stay = hx1 = h1(-1)) ----
    {
        const float x0 = xq0[0], x1 = xq1[0], x2 = xq2[0];
        if (bval) {
            const float* xp = xb + 8 * XSTRIDE;
            xq0[0] = xp[0]; xq1[0] = xp[1]; xq2[0] = xp[2];
        }
        const float pre = fmaf(wi0[2], x2, fmaf(wi0[1], x1, fmaf(wi0[0], x0, bias0)));
        const float a0 = fmaf(wh0[0], h0v[0], pre);
        const float a1 = fmaf(wh0[2], h0v[2], wh0[1] * h0v[1]);
        const float a2 = fmaf(wh0[4], h0v[4], wh0[3] * h0v[3]);
        h0j = tanh_fast((a0 + a1) + a2);
        #pragma unroll
        for (int k = 0; k < 5; k++) h0v[k] = __shfl_sync(0xffffffffu, h0j, k, 8);
    }

    // ---- main loop: t = 1 .. 2040, blocks of 8 (t0 = 8m+1 so t&7 = (u+1)&7) ----
    for (int t0 = 1; t0 < 2041; t0 += 8) {
        STEP(t0 + 0, 1);
        STEP(t0 + 1, 2);
        STEP(t0 + 2, 3);
        STEP(t0 + 3, 4);
        STEP(t0 + 4, 5);
        STEP(t0 + 5, 6);
        STEP(t0 + 6, 7);
        STEP(t0 + 7, 0);
    }

    // ---- tail: t = 2041 .. 2047 (compile-time constants, fully unrolled) ----
    #pragma unroll
    for (int t = 2041; t < 2048; t++) {
        STEP(t, (t) & 7);
    }

    // ---- epilogue: h1(2047) from h0v=h0(2047), h1v=h1(2046) ----
    {
        const float ua = fmaf(wi1[0], h0v[0], bias1);
        const float ub = fmaf(wi1[2], h0v[2], wi1[1] * h0v[1]);
        const float uc = fmaf(wi1[4], h0v[4], wi1[3] * h0v[3]);
        const float va = fmaf(wh1[1], h1v[1], wh1[0] * h1v[0]);
        const float vb = fmaf(wh1[4], h1v[4], fmaf(wh1[3], h1v[3], wh1[2] * h1v[2]));
        h1j = tanh_fast(((ua + ub) + uc) + (va + vb));
    }

    if (act) {
        outp[(T_LEN - 1) * OSTRIDE] = h1j;                 // out[2047]
        outp[T_LEN * OSTRIDE]           = h0j;             // h_n[0]
        outp[T_LEN * OSTRIDE + OSTRIDE] = h1j;             // h_n[1]
    }
#undef STEP
}

extern "C" void kernel_launch(void* const* d_in, const int* in_sizes, int n_in,
                              void* d_out, int out_size)
{
    const float* x     = (const float*)d_in[0];
    const float* hx    = (const float*)d_in[1];
    const float* w_ih0 = (const float*)d_in[2];
    const float* w_hh0 = (const float*)d_in[3];
    const float* b_ih0 = (const float*)d_in[4];
    const float* b_hh0 = (const float*)d_in[5];
    const float* w_ih1 = (const float*)d_in[6];
    const float* w_hh1 = (const float*)d_in[7];
    const float* b_ih1 = (const float*)d_in[8];
    const float* b_hh1 = (const float*)d_in[9];
    float* out = (float*)d_out;

    const int threads = 224;                              // 7 warps
    const int blocks  = (B_SZ * 8 + threads - 1) / threads;  // 147 (1 per SM)

    rnn2_kernel<<<blocks, threads>>>(x, hx, w_ih0, w_hh0, b_ih0, b_hh0,
                                     w_ih1, w_hh1, b_ih1, b_hh1, out);
}

// round 3
// speedup vs baseline: 1.1239x; 1.0621x over previous
#include <cuda_runtime.h>

// MultiLayerRNNModel: 2-layer tanh RNN, T=2048, B=4096, I=3, H=5
// out = concat(out[T,B,H], h_n[2,B,H])
//
// R3: replace the 10 per-step __shfl_sync broadcasts (serialized var-lat
// waits ~= 220 cyc/step) with shared-memory broadcast: 2 STS + syncwarp +
// 4 LDS per step, double-buffered on t&1. Groups of 8 lanes are intra-warp,
// so __syncwarp (not bar.sync) is sufficient.
// Layers stay software-pipelined: iteration t computes h0(t) and h1(t-1).

#define T_LEN   2048
#define B_SZ    4096
#define XSTRIDE (B_SZ * 3)
#define OSTRIDE (B_SZ * 5)
#define NGROUP  28          // 224 threads / 8 lanes per group
#define GSTRIDE 20          // floats per group slot (pad: conflict-free LDS)

__device__ __forceinline__ float tanh_fast(float v) {
    float y;
    asm("tanh.approx.f32 %0, %1;" : "=f"(y) : "f"(v));
    return y;
}

__global__ __launch_bounds__(224, 1)
void rnn2_kernel(const float* __restrict__ x,
                 const float* __restrict__ hx,
                 const float* __restrict__ w_ih0,
                 const float* __restrict__ w_hh0,
                 const float* __restrict__ b_ih0,
                 const float* __restrict__ b_hh0,
                 const float* __restrict__ w_ih1,
                 const float* __restrict__ w_hh1,
                 const float* __restrict__ b_ih1,
                 const float* __restrict__ b_hh1,
                 float* __restrict__ out)
{
    __shared__ __align__(16) float buf[2][NGROUP][GSTRIDE];

    const int tid  = blockIdx.x * blockDim.x + threadIdx.x;
    const int b    = tid >> 3;                 // batch element
    const int j    = threadIdx.x & 7;          // hidden unit (active j<5)
    const int g    = threadIdx.x >> 3;         // group within block
    const bool bval = (b < B_SZ);
    const bool act  = bval && (j < 5);
    const int  jj   = (j < 5) ? j : 0;

    // per-lane weights (row jj)
    float wi0[3], wh0[5], wi1[5], wh1[5];
    #pragma unroll
    for (int k = 0; k < 3; k++) wi0[k] = w_ih0[jj * 3 + k];
    #pragma unroll
    for (int k = 0; k < 5; k++) {
        wh0[k] = w_hh0[jj * 5 + k];
        wi1[k] = w_ih1[jj * 5 + k];
        wh1[k] = w_hh1[jj * 5 + k];
    }
    const float bias0 = b_ih0[jj] + b_hh0[jj];
    const float bias1 = b_ih1[jj] + b_hh1[jj];

    // replicated state: at loop head h0v = h0(t-1), h1v = h1(t-2)
    float h0v[5], h1v[5];
    #pragma unroll
    for (int k = 0; k < 5; k++) {
        h0v[k] = bval ? hx[b * 5 + k]            : 0.f;
        h1v[k] = bval ? hx[B_SZ * 5 + b * 5 + k] : 0.f;
    }

    const float* xb   = x + b * 3;
    float*       outp = out + b * 5 + j;

    // x prefetch queue, slot p holds x[t] with t&7 == p
    float xq0[8], xq1[8], xq2[8];
    #pragma unroll
    for (int p = 0; p < 8; p++) {
        const float* xp = xb + p * XSTRIDE;
        xq0[p] = bval ? xp[0] : 0.f;
        xq1[p] = bval ? xp[1] : 0.f;
        xq2[p] = bval ? xp[2] : 0.f;
    }

    float h0j = 0.f, h1j = 0.f;

// One pipelined step: computes h0(t) and h1(t-1).
// XP == t&7 (x-queue phase), BP == t&1 (smem buffer parity); both literal.
#define STEP(t, XP, BP) {                                                     \
    const float x0 = xq0[XP], x1 = xq1[XP], x2 = xq2[XP];                     \
    if (bval && (t) + 8 < T_LEN) {                                            \
        const float* xp = xb + ((t) + 8) * XSTRIDE;                           \
        xq0[XP] = xp[0]; xq1[XP] = xp[1]; xq2[XP] = xp[2];                    \
    }                                                                         \
    /* layer-0 pre-activation for h0(t) */                                    \
    const float pre = fmaf(wi0[2], x2, fmaf(wi0[1], x1, fmaf(wi0[0], x0, bias0))); \
    const float a0 = fmaf(wh0[0], h0v[0], pre);                               \
    const float a1 = fmaf(wh0[2], h0v[2], wh0[1] * h0v[1]);                   \
    const float a2 = fmaf(wh0[4], h0v[4], wh0[3] * h0v[3]);                   \
    const float s  = (a0 + a1) + a2;                                          \
    /* layer-1 pre-activation for h1(t-1): h0v=h0(t-1), h1v=h1(t-2) */        \
    const float ua = fmaf(wi1[0], h0v[0], bias1);                             \
    const float ub = fmaf(wi1[2], h0v[2], wi1[1] * h0v[1]);                   \
    const float uc = fmaf(wi1[4], h0v[4], wi1[3] * h0v[3]);                   \
    const float va = fmaf(wh1[1], h1v[1], wh1[0] * h1v[0]);                   \
    const float vb = fmaf(wh1[4], h1v[4], fmaf(wh1[3], h1v[3], wh1[2] * h1v[2])); \
    const float u  = ((ua + ub) + uc) + (va + vb);                            \
    h0j = tanh_fast(s);                                                       \
    h1j = tanh_fast(u);                                                       \
    buf[BP][g][j]     = h0j;  /* lanes j>=5 write pad slots: harmless */      \
    buf[BP][g][8 + j] = h1j;                                                  \
    __syncwarp();                                                             \
    { const float4 q0 = *(const float4*)&buf[BP][g][0];                       \
      h0v[0] = q0.x; h0v[1] = q0.y; h0v[2] = q0.z; h0v[3] = q0.w;             \
      h0v[4] = buf[BP][g][4];                                                 \
      const float4 q1 = *(const float4*)&buf[BP][g][8];                       \
      h1v[0] = q1.x; h1v[1] = q1.y; h1v[2] = q1.z; h1v[3] = q1.w;             \
      h1v[4] = buf[BP][g][12]; }                                              \
    if (act) outp[((t) - 1) * OSTRIDE] = h1j;                                 \
}

    // ---- prologue: t = 0, layer 0 only; broadcast h0(0) via buffer 0 ----
    {
        const float x0 = xq0[0], x1 = xq1[0], x2 = xq2[0];
        if (bval) {
            const float* xp = xb + 8 * XSTRIDE;
            xq0[0] = xp[0]; xq1[0] = xp[1]; xq2[0] = xp[2];
        }
        const float pre = fmaf(wi0[2], x2, fmaf(wi0[1], x1, fmaf(wi0[0], x0, bias0)));
        const float a0 = fmaf(wh0[0], h0v[0], pre);
        const float a1 = fmaf(wh0[2], h0v[2], wh0[1] * h0v[1]);
        const float a2 = fmaf(wh0[4], h0v[4], wh0[3] * h0v[3]);
        h0j = tanh_fast((a0 + a1) + a2);
        buf[0][g][j] = h0j;
        __syncwarp();
        const float4 q0 = *(const float4*)&buf[0][g][0];
        h0v[0] = q0.x; h0v[1] = q0.y; h0v[2] = q0.z; h0v[3] = q0.w;
        h0v[4] = buf[0][g][4];
    }

    // ---- main loop: t = 1 .. 2040 in blocks of 8 (t0 = 8m+1) ----
    for (int t0 = 1; t0 < 2041; t0 += 8) {
        STEP(t0 + 0, 1, 1);
        STEP(t0 + 1, 2, 0);
        STEP(t0 + 2, 3, 1);
        STEP(t0 + 3, 4, 0);
        STEP(t0 + 4, 5, 1);
        STEP(t0 + 5, 6, 0);
        STEP(t0 + 6, 7, 1);
        STEP(t0 + 7, 0, 0);
    }

    // ---- tail: t = 2041 .. 2047 ----
    STEP(2041, 1, 1);
    STEP(2042, 2, 0);
    STEP(2043, 3, 1);
    STEP(2044, 4, 0);
    STEP(2045, 5, 1);
    STEP(2046, 6, 0);
    STEP(2047, 7, 1);

    // ---- epilogue: h1(2047) from h0v=h0(2047), h1v=h1(2046) ----
    {
        const float ua = fmaf(wi1[0], h0v[0], bias1);
        const float ub = fmaf(wi1[2], h0v[2], wi1[1] * h0v[1]);
        const float uc = fmaf(wi1[4], h0v[4], wi1[3] * h0v[3]);
        const float va = fmaf(wh1[1], h1v[1], wh1[0] * h1v[0]);
        const float vb = fmaf(wh1[4], h1v[4], fmaf(wh1[3], h1v[3], wh1[2] * h1v[2]));
        h1j = tanh_fast(((ua + ub) + uc) + (va + vb));
    }

    if (act) {
        outp[(T_LEN - 1) * OSTRIDE]     = h1j;     // out[2047]
        outp[T_LEN * OSTRIDE]           = h0j;     // h_n[0]
        outp[T_LEN * OSTRIDE + OSTRIDE] = h1j;     // h_n[1]
    }
#undef STEP
}

extern "C" void kernel_launch(void* const* d_in, const int* in_sizes, int n_in,
                              void* d_out, int out_size)
{
    const float* x     = (const float*)d_in[0];
    const float* hx    = (const float*)d_in[1];
    const float* w_ih0 = (const float*)d_in[2];
    const float* w_hh0 = (const float*)d_in[3];
    const float* b_ih0 = (const float*)d_in[4];
    const float* b_hh0 = (const float*)d_in[5];
    const float* w_ih1 = (const float*)d_in[6];
    const float* w_hh1 = (const float*)d_in[7];
    const float* b_ih1 = (const float*)d_in[8];
    const float* b_hh1 = (const float*)d_in[9];
    float* out = (float*)d_out;

    const int threads = 224;                                 // 7 warps
    const int blocks  = (B_SZ * 8 + threads - 1) / threads;  // 147

    rnn2_kernel<<<blocks, threads>>>(x, hx, w_ih0, w_hh0, b_ih0, b_hh0,
                                     w_ih1, w_hh1, b_ih1, b_hh1, out);
}